// round 15
// baseline (speedup 1.0000x reference)
#include <cuda_runtime.h>

// LightConv depthwise causal conv, GB300 sm_103a — float4 register pipeline.
// x: [T=4096, B=8, C=1024] fp32, weight: [H=16, K=31] fp32 (softmax over K per head).
// out[t,b,c] = sum_k softmax(w)[c/64,k] * x[t-30+k, b, c]   (x = 0 for t < 0)
//
// R14 structural change vs R9 (51.2us): each thread owns a float4 column
// (4 adjacent channels, same head) instead of float2. Per step: 1 LDG.128 +
// 1 STG.128 + 62 FFMA2. Rationale: measured issue-cost model showed STG.64
// (~7.75 issue cyc) made memory-op issue the binding resource at 3 warps/SMSP
// (fma capped ~58%). STG.128 halves store issue cost per output; FMA slots now
// dominate issue -> FMA pipe becomes the limiter. Registers: acc[32]x4 + wv 62
// + xb[8]x4 ~ 242 -> occupancy 1 (255-reg cap). One warp/SMSP suffices: 31-way
// independent FFMA2 ILP sustains rt=2 pipe; PF=8 steps ~ 1000cyc covers DRAM.
// Grid 16 x 9 = 144 blocks ~ one balanced wave on 148 SMs (TT=480, NJ=15,
// last tile clamped to t0=3616, both %32==0). Ring algebra identical to R9:
// 32-slot acc ring, slot g&31 init'd by w[0] 30 steps early, drained by w[30].

#define T_DIM   4096
#define B_DIM   8
#define C_DIM   1024
#define K_TAPS  31
#define SLOTS   32                        // accumulator ring size (power of 2)
#define PF      8                         // prefetch ring size, divides SLOTS
#define ROW4    ((B_DIM * C_DIM) / 4)     // float4 (ulonglong2) per t-row = 2048
#define THREADS 128
#define NJ      15                        // store stages per tile
#define TT      (NJ * SLOTS)              // 480 outputs per tile
#define GRIDX   (ROW4 / THREADS)          // 16
#define GRIDY   9                         // 8*480=3840 <4096 -> 9 tiles, last clamped
#define NSTAGES (NJ + 1)                  // + warm-up stage

typedef unsigned long long u64;
typedef unsigned int u32;

__device__ __forceinline__ u64 ffma2(u64 a, u64 b, u64 c) {
    u64 d;
    asm("fma.rn.f32x2 %0, %1, %2, %3;" : "=l"(d) : "l"(a), "l"(b), "l"(c));
    return d;
}
__device__ __forceinline__ u64 fmul2(u64 a, u64 b) {
    u64 d;
    asm("mul.rn.f32x2 %0, %1, %2;" : "=l"(d) : "l"(a), "l"(b));
    return d;
}

__global__ __launch_bounds__(THREADS, 1) void lightconv_kernel(
    const float* __restrict__ x, const float* __restrict__ wg,
    float* __restrict__ out)
{
    const int tid = threadIdx.x;
    const int c4  = blockIdx.x * THREADS + tid;            // this thread's float4 column
    const int by  = blockIdx.y;
    const int t0  = (by < GRIDY - 1) ? by * TT : (T_DIM - TT);  // 3616 % 32 == 0
    const int h   = ((c4 * 4) & (C_DIM - 1)) >> 6;         // head (4 ch share it)

    // ---- per-thread softmax of this head's 31 taps, packed {w,w} ----
    float wf[K_TAPS];
    float mx = -3.402823466e38f;
#pragma unroll
    for (int k = 0; k < K_TAPS; k++) {
        wf[k] = __ldg(wg + h * K_TAPS + k);
        mx = fmaxf(mx, wf[k]);
    }
    float ssum = 0.0f;
#pragma unroll
    for (int k = 0; k < K_TAPS; k++) { wf[k] = expf(wf[k] - mx); ssum += wf[k]; }
    const float inv = 1.0f / ssum;
    u64 wv[K_TAPS];
#pragma unroll
    for (int k = 0; k < K_TAPS; k++) {
        u32 b = __float_as_uint(wf[k] * inv);
        wv[k] = ((u64)b << 32) | (u64)b;
    }

    const ulonglong2* __restrict__ px = (const ulonglong2*)x + c4;  // per-thread column
    ulonglong2* __restrict__ po       = (ulonglong2*)out + c4;
    const int s0 = t0 - SLOTS;                             // first warm-up row

    ulonglong2 acc[SLOTS];
#pragma unroll
    for (int u = 0; u < SLOTS; u++) { acc[u].x = 0ull; acc[u].y = 0ull; }

    // ---- initial prefetch: rows s0 .. s0+7 (zeros for t<0, tile 0 only) ----
    ulonglong2 xb[PF];
#pragma unroll
    for (int p = 0; p < PF; p++) {
        const int tr = s0 + p;
        if (tr >= 0) xb[p] = px[(long)tr * ROW4];
        else         { xb[p].x = 0ull; xb[p].y = 0ull; }
    }

    // ---- stages: j=0 warm-up (no stores), j=1..NJ store 32 rows each ----
#pragma unroll 1
    for (int j = 0; j < NSTAGES; j++) {
        const int rowbase = s0 + j * SLOTS;                // row of step u=0
        const ulonglong2* __restrict__ pfp = px + (long)(rowbase + PF) * ROW4;
        ulonglong2* __restrict__ q         = po + (long)rowbase * ROW4;
        const bool ston = (j > 0);
        const bool pfon = (j + 1 < NSTAGES);               // next stage exists

#pragma unroll
        for (int u = 0; u < SLOTS; u++) {
            ulonglong2 xv = xb[u & (PF - 1)];
            // refill row rowbase+u+PF. In the last stage, refills at
            // u < SLOTS-PF feed THIS stage (in-bounds); the final PF refills
            // feed a nonexistent stage -> predicated off.
            if (pfon || u < SLOTS - PF) {
                const int tr = rowbase + u + PF;
                if (tr >= 0) xb[u & (PF - 1)] = pfp[(long)u * ROW4];
                else         { xb[u & (PF - 1)].x = 0ull; xb[u & (PF - 1)].y = 0ull; }
            }
            // drain slot u: out[rowbase+u] = acc + w[30]*x[rowbase+u]
            ulonglong2 o;
            o.x = ffma2(wv[30], xv.x, acc[u].x);
            o.y = ffma2(wv[30], xv.y, acc[u].y);
            if (ston) q[(long)u * ROW4] = o;               // STG.128, no bound check
            // scatter middle taps (compile-time ring indices)
#pragma unroll
            for (int d = 1; d <= 29; d++) {
                const int s = (u + d) & (SLOTS - 1);
                acc[s].x = ffma2(wv[30 - d], xv.x, acc[s].x);
                acc[s].y = ffma2(wv[30 - d], xv.y, acc[s].y);
            }
            // first tap initializes the slot for out[rowbase+u+30]
            const int si = (u + 30) & (SLOTS - 1);
            acc[si].x = fmul2(wv[0], xv.x);
            acc[si].y = fmul2(wv[0], xv.y);
        }
    }
}

extern "C" void kernel_launch(void* const* d_in, const int* in_sizes, int n_in,
                              void* d_out, int out_size) {
    const float* x = (const float*)d_in[0];
    const float* w = (const float*)d_in[1];
    if (n_in >= 2 && in_sizes[0] < in_sizes[1]) {   // robustness: x is the big tensor
        x = (const float*)d_in[1];
        w = (const float*)d_in[0];
    }
    dim3 grid(GRIDX, GRIDY);                        // (16, 9) = 144 blocks, one wave
    lightconv_kernel<<<grid, THREADS>>>(x, w, (float*)d_out);
}

// round 16
// speedup vs baseline: 1.5277x; 1.5277x over previous
#include <cuda_runtime.h>

// LightConv depthwise causal conv, GB300 sm_103a — pure register pipeline.
// x: [T=4096, B=8, C=1024] fp32, weight: [H=16, K=31] fp32 (softmax over K per head).
// out[t,b,c] = sum_k softmax(w)[c/64,k] * x[t-30+k, b, c]   (x = 0 for t < 0)
//
// EXACT R9 record configuration (51.2us measured; best of 6 variants tried):
//  - per thread one float2 column; 32-slot rolling accumulator ring (&31):
//    slot g&31 initialized by tap w[0] 30 steps early, drained by tap w[30]
//    at step g, taps w[29..1] scattered in between.
//  - 8-slot register prefetch ring (distance 8 steps).
//  - __launch_bounds__(128,3): 168 regs, 3 blocks/SM = 12 warps/SM.
//  - TT=320 (warm-up + 10 store stages), grid (32,13)=416 blocks ~ one wave;
//    last tile clamped to t0=3776 (%32==0; duplicate stores, identical values).
//  - guarded refills (tr>=0) everywhere — measured faster than peeled variants
//    (R10/R11 code-layout experiments regressed; I$ and codegen sensitivity).
//
// R15 single probe: head index derived from (threadIdx.x >> 5) only, making it
// provably warp-uniform to ptxas's uniformity analysis -> softmax/tap values
// become candidates for uniform-register allocation. If regs drop (<150), an
// occupancy-4 variant becomes viable next round. Failure mode: identical
// codegen to R9 (same value, same semantics).

#define T_DIM   4096
#define B_DIM   8
#define C_DIM   1024
#define K_TAPS  31
#define SLOTS   32                        // accumulator ring size (power of 2)
#define PF      8                         // prefetch ring size, divides SLOTS
#define ROW     ((B_DIM * C_DIM) / 2)     // u64 per t-row = 4096
#define BC2     ((B_DIM * C_DIM) / 2)
#define THREADS 128
#define NJ      10                        // store stages per tile
#define TT      (NJ * SLOTS)              // 320 outputs per tile
#define GRIDY   13                        // last tile clamped to t0 = 3776
#define NSTAGES (NJ + 1)                  // + warm-up stage

typedef unsigned long long u64;
typedef unsigned int u32;

__device__ __forceinline__ u64 ffma2(u64 a, u64 b, u64 c) {
    u64 d;
    asm("fma.rn.f32x2 %0, %1, %2, %3;" : "=l"(d) : "l"(a), "l"(b), "l"(c));
    return d;
}
__device__ __forceinline__ u64 fmul2(u64 a, u64 b) {
    u64 d;
    asm("mul.rn.f32x2 %0, %1, %2;" : "=l"(d) : "l"(a), "l"(b));
    return d;
}

__global__ __launch_bounds__(THREADS, 3) void lightconv_kernel(
    const float* __restrict__ x, const float* __restrict__ wg,
    float* __restrict__ out)
{
    const int tid = threadIdx.x;
    const int bc2 = blockIdx.x * THREADS + tid;            // this thread's u64 column
    const int by  = blockIdx.y;
    const int t0  = (by < GRIDY - 1) ? by * TT : (T_DIM - TT);  // 3776 % 32 == 0

    // Head index, warp-uniform BY CONSTRUCTION (depends on tid only via tid>>5):
    // a warp spans 32 u64 columns = 64 channels = exactly one head.
    const int warp = tid >> 5;
    const int h = (((blockIdx.x * THREADS + warp * 32) * 2) & (C_DIM - 1)) >> 6;

    // ---- per-thread softmax of this head's 31 taps, packed {w,w} ----
    float wf[K_TAPS];
    float mx = -3.402823466e38f;
#pragma unroll
    for (int k = 0; k < K_TAPS; k++) {
        wf[k] = __ldg(wg + h * K_TAPS + k);
        mx = fmaxf(mx, wf[k]);
    }
    float ssum = 0.0f;
#pragma unroll
    for (int k = 0; k < K_TAPS; k++) { wf[k] = expf(wf[k] - mx); ssum += wf[k]; }
    const float inv = 1.0f / ssum;
    u64 wv[K_TAPS];
#pragma unroll
    for (int k = 0; k < K_TAPS; k++) {
        u32 b = __float_as_uint(wf[k] * inv);
        wv[k] = ((u64)b << 32) | (u64)b;
    }

    const u64* __restrict__ px = (const u64*)x + bc2;      // per-thread column
    u64* __restrict__ po       = (u64*)out + bc2;
    const int s0 = t0 - SLOTS;                             // first warm-up row

    u64 acc[SLOTS];
#pragma unroll
    for (int u = 0; u < SLOTS; u++) acc[u] = 0ull;

    // ---- initial prefetch: rows s0 .. s0+7 (zeros for t<0, tile 0 only) ----
    u64 xb[PF];
#pragma unroll
    for (int p = 0; p < PF; p++) {
        const int tr = s0 + p;
        xb[p] = (tr >= 0) ? px[(long)tr * ROW] : 0ull;
    }

    // ---- stages: j=0 warm-up (no stores), j=1..NJ store 32 rows each ----
#pragma unroll 1
    for (int j = 0; j < NSTAGES; j++) {
        const int rowbase = s0 + j * SLOTS;                // row of step u=0
        const u64* __restrict__ pfp = px + (long)(rowbase + PF) * ROW;
        u64* __restrict__ q         = po + (long)rowbase * ROW;
        const bool ston = (j > 0);
        const bool pfon = (j + 1 < NSTAGES);               // next stage exists

#pragma unroll
        for (int u = 0; u < SLOTS; u++) {
            u64 xv = xb[u & (PF - 1)];
            // refill row rowbase+u+PF. In the last stage, refills at
            // u < SLOTS-PF feed THIS stage (in-bounds); the final PF refills
            // feed a nonexistent stage -> predicated off.
            if (pfon || u < SLOTS - PF) {
                const int tr = rowbase + u + PF;
                xb[u & (PF - 1)] = (tr >= 0) ? pfp[(long)u * ROW] : 0ull;
            }
            // drain slot u: out[rowbase+u] = acc + w[30]*x[rowbase+u]
            u64 o = ffma2(wv[30], xv, acc[u]);
            if (ston) q[(long)u * ROW] = o;                // no bound check
            // scatter middle taps (compile-time ring indices)
#pragma unroll
            for (int d = 1; d <= 29; d++) {
                acc[(u + d) & (SLOTS - 1)] =
                    ffma2(wv[30 - d], xv, acc[(u + d) & (SLOTS - 1)]);
            }
            // first tap initializes the slot for out[rowbase+u+30]
            acc[(u + 30) & (SLOTS - 1)] = fmul2(wv[0], xv);
        }
    }
}

extern "C" void kernel_launch(void* const* d_in, const int* in_sizes, int n_in,
                              void* d_out, int out_size) {
    const float* x = (const float*)d_in[0];
    const float* w = (const float*)d_in[1];
    if (n_in >= 2 && in_sizes[0] < in_sizes[1]) {   // robustness: x is the big tensor
        x = (const float*)d_in[1];
        w = (const float*)d_in[0];
    }
    dim3 grid(BC2 / THREADS, GRIDY);                // (32, 13) = 416 blocks, one wave
    lightconv_kernel<<<grid, THREADS>>>(x, w, (float*)d_out);
}